// round 2
// baseline (speedup 1.0000x reference)
#include <cuda_runtime.h>
#include <math.h>

#define BATCH 2
#define SEQ 2048
#define DIM 2048
#define NH 16
#define NKV 4
#define HD 128
#define QKV_DIM 3072      /* (16 + 2*4) * 128 */
#define TOK (BATCH*SEQ)   /* 4096 */

#define QT 64
#define KT 64
#define FLASH_SMEM ((3*QT*HD + QT*KT + 3*QT)*4)

// Scratch (device globals; no runtime allocation)
__device__ float g_xn[(size_t)TOK * DIM];
__device__ float g_qkv[(size_t)TOK * QKV_DIM];
__device__ float g_attn[(size_t)TOK * DIM];

// ---------------------------------------------------------------------------
// RMSNorm: one block per token row. 256 threads, 2 float4 each (2048 floats).
// ---------------------------------------------------------------------------
__global__ __launch_bounds__(256) void rmsnorm_kernel(const float* __restrict__ x,
                                                      const float* __restrict__ w,
                                                      float* __restrict__ out) {
    int row = blockIdx.x;
    int t = threadIdx.x;
    const float4* xr = (const float4*)(x + (size_t)row * DIM);
    float4 v[2];
    float s = 0.f;
#pragma unroll
    for (int i = 0; i < 2; i++) {
        v[i] = xr[t + i * 256];
        s += v[i].x * v[i].x + v[i].y * v[i].y + v[i].z * v[i].z + v[i].w * v[i].w;
    }
    __shared__ float red[8];
#pragma unroll
    for (int o = 16; o > 0; o >>= 1) s += __shfl_xor_sync(~0u, s, o);
    if ((t & 31) == 0) red[t >> 5] = s;
    __syncthreads();
    if (t < 32) {
        float ss = (t < 8) ? red[t] : 0.f;
#pragma unroll
        for (int o = 4; o > 0; o >>= 1) ss += __shfl_xor_sync(~0u, ss, o);
        if (t == 0) red[0] = rsqrtf(ss / (float)DIM + 1e-6f);
    }
    __syncthreads();
    float rs = red[0];
    float4* o4 = (float4*)(out + (size_t)row * DIM);
    const float4* w4 = (const float4*)w;
#pragma unroll
    for (int i = 0; i < 2; i++) {
        float4 wv = w4[t + i * 256];
        float4 r;
        r.x = v[i].x * rs * wv.x;
        r.y = v[i].y * rs * wv.y;
        r.z = v[i].z * rs * wv.z;
        r.w = v[i].w * rs * wv.w;
        o4[t + i * 256] = r;
    }
}

// ---------------------------------------------------------------------------
// NT GEMM: C[m][n] = sum_k A[m][k] * B[n][k]. A: MxK row-major, B: NxK row-major.
// Block tile 128x128, BK=16, 256 threads, 8x8 per-thread micro-tile.
// ---------------------------------------------------------------------------
#define BM 128
#define BN 128
#define BK 16

__global__ __launch_bounds__(256) void gemm_nt(const float* __restrict__ A,
                                               const float* __restrict__ B,
                                               float* __restrict__ C,
                                               int M, int N, int K) {
    __shared__ float As[BK][BM];
    __shared__ float Bs[BK][BN];
    int m0 = blockIdx.y * BM;
    int n0 = blockIdx.x * BN;
    int t = threadIdx.x;
    int tx = t & 15;   // 0..15 -> 8 cols each
    int ty = t >> 4;   // 0..15 -> 8 rows each
    float acc[8][8] = {};

    for (int k0 = 0; k0 < K; k0 += BK) {
        // load A tile (128 rows x 16 k) and B tile, transposed into [k][mn]
#pragma unroll
        for (int i = 0; i < 2; i++) {
            int idx = t + i * 256;        // 0..511
            int r = idx >> 2;             // 0..127
            int kq = idx & 3;             // float4 group within 16 k's
            float4 a = *(const float4*)(A + (size_t)(m0 + r) * K + k0 + 4 * kq);
            As[4 * kq + 0][r] = a.x;
            As[4 * kq + 1][r] = a.y;
            As[4 * kq + 2][r] = a.z;
            As[4 * kq + 3][r] = a.w;
            float4 b = *(const float4*)(B + (size_t)(n0 + r) * K + k0 + 4 * kq);
            Bs[4 * kq + 0][r] = b.x;
            Bs[4 * kq + 1][r] = b.y;
            Bs[4 * kq + 2][r] = b.z;
            Bs[4 * kq + 3][r] = b.w;
        }
        __syncthreads();

        float a[8], bb[8];
#pragma unroll
        for (int k = 0; k < BK; k++) {
            *(float4*)&a[0] = *(const float4*)&As[k][8 * ty];
            *(float4*)&a[4] = *(const float4*)&As[k][8 * ty + 4];
            *(float4*)&bb[0] = *(const float4*)&Bs[k][8 * tx];
            *(float4*)&bb[4] = *(const float4*)&Bs[k][8 * tx + 4];
#pragma unroll
            for (int i = 0; i < 8; i++)
#pragma unroll
                for (int j = 0; j < 8; j++)
                    acc[i][j] += a[i] * bb[j];
        }
        __syncthreads();
    }

#pragma unroll
    for (int i = 0; i < 8; i++) {
        size_t row = (size_t)(m0 + 8 * ty + i) * N + n0 + 8 * tx;
        *(float4*)&C[row] = make_float4(acc[i][0], acc[i][1], acc[i][2], acc[i][3]);
        *(float4*)&C[row + 4] = make_float4(acc[i][4], acc[i][5], acc[i][6], acc[i][7]);
    }
}

// ---------------------------------------------------------------------------
// RoPE in-place on q and k portions of qkv. One block per token.
// freqs: [SEQ][64][2] = (cos, sin) per pair.
// ---------------------------------------------------------------------------
__global__ __launch_bounds__(256) void rope_kernel(float* __restrict__ qkv,
                                                   const float* __restrict__ freqs) {
    int tok = blockIdx.x;
    int s = tok % SEQ;
    for (int idx = threadIdx.x; idx < (NH + NKV) * (HD / 2); idx += blockDim.x) {
        int head = idx >> 6;    // pair-groups of 64
        int p = idx & 63;
        float* ptr;
        if (head < NH)
            ptr = qkv + (size_t)tok * QKV_DIM + head * HD;
        else
            ptr = qkv + (size_t)tok * QKV_DIM + NH * HD + (head - NH) * HD;
        float c  = freqs[(s * 64 + p) * 2 + 0];
        float sn = freqs[(s * 64 + p) * 2 + 1];
        float xr = ptr[2 * p];
        float xi = ptr[2 * p + 1];
        ptr[2 * p]     = xr * c - xi * sn;
        ptr[2 * p + 1] = xr * sn + xi * c;
    }
}

// ---------------------------------------------------------------------------
// Flash attention (causal, GQA). Grid: (SEQ/QT, NH, BATCH). 256 threads.
// Q tile 64 rows; KV tiles of 64 up to the diagonal. fp32 throughout.
// warp w owns rows 8w..8w+7; lane owns cols 4*lane..4*lane+3 of head_dim.
// ---------------------------------------------------------------------------
__global__ __launch_bounds__(256) void flash_kernel(const float* __restrict__ qkv,
                                                    float* __restrict__ attn) {
    extern __shared__ float sm[];
    float* Qs = sm;                    // QT*HD
    float* Ks = Qs + QT * HD;          // KT*HD
    float* Vs = Ks + KT * HD;          // KT*HD
    float* Ss = Vs + KT * HD;          // QT*KT
    float* mrow = Ss + QT * KT;        // QT
    float* lrow = mrow + QT;           // QT
    float* arow = lrow + QT;           // QT

    int qt = gridDim.x - 1 - blockIdx.x;   // heavy tiles first
    int h = blockIdx.y;
    int b = blockIdx.z;
    int kvh = h / (NH / NKV);
    int t = threadIdx.x;
    int lane = t & 31, w = t >> 5;
    int q0 = qt * QT;

    const float* qbase = qkv + (size_t)b * SEQ * QKV_DIM + (size_t)h * HD;
    const float* kbase = qkv + (size_t)b * SEQ * QKV_DIM + NH * HD + (size_t)kvh * HD;
    const float* vbase = kbase + NKV * HD;

    // load Q tile
    for (int i = t; i < QT * (HD / 4); i += 256) {
        int r = i / (HD / 4), c4 = i % (HD / 4);
        *(float4*)&Qs[r * HD + 4 * c4] =
            *(const float4*)&qbase[(size_t)(q0 + r) * QKV_DIM + 4 * c4];
    }
    if (t < QT) { mrow[t] = -1e30f; lrow[t] = 0.f; }

    float acc[8][4] = {};
    const float scale = 0.08838834764831845f;  // 1/sqrt(128)

    for (int kt = 0; kt <= qt; kt++) {
        int k0 = kt * KT;
        __syncthreads();  // protect Ks/Vs/Ss reuse; also covers Q/m/l init on iter 0
        for (int i = t; i < KT * (HD / 4); i += 256) {
            int r = i / (HD / 4), c4 = i % (HD / 4);
            *(float4*)&Ks[r * HD + 4 * c4] =
                *(const float4*)&kbase[(size_t)(k0 + r) * QKV_DIM + 4 * c4];
            *(float4*)&Vs[r * HD + 4 * c4] =
                *(const float4*)&vbase[(size_t)(k0 + r) * QKV_DIM + 4 * c4];
        }
        __syncthreads();

        // S = Q K^T (64x64), 4x4 micro-tile per thread
        {
            int ti = t & 15, tj = t >> 4;
            int r0 = 4 * tj, c0 = 4 * ti;
            float s4[4][4] = {};
#pragma unroll 4
            for (int kk = 0; kk < HD / 4; kk++) {
                float4 q4[4], k4[4];
#pragma unroll
                for (int i = 0; i < 4; i++) q4[i] = *(const float4*)&Qs[(r0 + i) * HD + 4 * kk];
#pragma unroll
                for (int j = 0; j < 4; j++) k4[j] = *(const float4*)&Ks[(c0 + j) * HD + 4 * kk];
#pragma unroll
                for (int i = 0; i < 4; i++)
#pragma unroll
                    for (int j = 0; j < 4; j++)
                        s4[i][j] += q4[i].x * k4[j].x + q4[i].y * k4[j].y +
                                    q4[i].z * k4[j].z + q4[i].w * k4[j].w;
            }
#pragma unroll
            for (int i = 0; i < 4; i++)
#pragma unroll
                for (int j = 0; j < 4; j++) {
                    float v = s4[i][j] * scale;
                    if (k0 + c0 + j > q0 + r0 + i) v = -1e30f;
                    Ss[(r0 + i) * KT + c0 + j] = v;
                }
        }
        __syncthreads();

        // online softmax per row (threads 0..63)
        if (t < QT) {
            int r = t;
            float mold = mrow[r];
            float mnew = mold;
#pragma unroll 8
            for (int j = 0; j < KT; j++) mnew = fmaxf(mnew, Ss[r * KT + j]);
            float alpha = __expf(mold - mnew);
            float rs = 0.f;
#pragma unroll 8
            for (int j = 0; j < KT; j++) {
                float p = __expf(Ss[r * KT + j] - mnew);
                Ss[r * KT + j] = p;
                rs += p;
            }
            lrow[r] = lrow[r] * alpha + rs;
            mrow[r] = mnew;
            arow[r] = alpha;
        }
        __syncthreads();

        // rescale + P @ V
        {
            int c0 = 4 * lane;
#pragma unroll
            for (int i = 0; i < 8; i++) {
                float a = arow[8 * w + i];
#pragma unroll
                for (int j = 0; j < 4; j++) acc[i][j] *= a;
            }
            for (int j = 0; j < KT; j++) {
                float4 v4 = *(const float4*)&Vs[j * HD + c0];
#pragma unroll
                for (int i = 0; i < 8; i++) {
                    float p = Ss[(8 * w + i) * KT + j];
                    acc[i][0] += p * v4.x;
                    acc[i][1] += p * v4.y;
                    acc[i][2] += p * v4.z;
                    acc[i][3] += p * v4.w;
                }
            }
        }
    }

    // epilogue: normalize and store to attn[b][s][h*128 + c]
    {
        int c0 = 4 * lane;
#pragma unroll
        for (int i = 0; i < 8; i++) {
            int r = 8 * w + i;
            float inv = 1.f / lrow[r];
            float4 o;
            o.x = acc[i][0] * inv;
            o.y = acc[i][1] * inv;
            o.z = acc[i][2] * inv;
            o.w = acc[i][3] * inv;
            *(float4*)&attn[(size_t)(b * SEQ + q0 + r) * DIM + h * HD + c0] = o;
        }
    }
}

// ---------------------------------------------------------------------------
extern "C" void kernel_launch(void* const* d_in, const int* in_sizes, int n_in,
                              void* d_out, int out_size) {
    (void)in_sizes; (void)n_in; (void)out_size;
    const float* x      = (const float*)d_in[0];
    const float* freqs  = (const float*)d_in[1];
    const float* norm_w = (const float*)d_in[2];
    const float* wqkv   = (const float*)d_in[3];
    const float* wo     = (const float*)d_in[4];
    float* out = (float*)d_out;

    float *xn, *qkv, *attn;
    cudaGetSymbolAddress((void**)&xn, g_xn);
    cudaGetSymbolAddress((void**)&qkv, g_qkv);
    cudaGetSymbolAddress((void**)&attn, g_attn);

    rmsnorm_kernel<<<TOK, 256>>>(x, norm_w, xn);

    gemm_nt<<<dim3(QKV_DIM / BN, TOK / BM), 256>>>(xn, wqkv, qkv, TOK, QKV_DIM, DIM);

    rope_kernel<<<TOK, 256>>>(qkv, freqs);

    cudaFuncSetAttribute(flash_kernel, cudaFuncAttributeMaxDynamicSharedMemorySize, FLASH_SMEM);
    flash_kernel<<<dim3(SEQ / QT, NH, BATCH), 256, FLASH_SMEM>>>(qkv, attn);

    gemm_nt<<<dim3(DIM / BN, TOK / BM), 256>>>(attn, wo, out, TOK, DIM, DIM);
}

// round 3
// speedup vs baseline: 1.3170x; 1.3170x over previous
#include <cuda_runtime.h>
#include <math.h>
#include <stdint.h>

#define BATCH 2
#define SEQ 2048
#define DIM 2048
#define NH 16
#define NKV 4
#define HD 128
#define QKV_DIM 3072      /* (16 + 2*4) * 128 */
#define TOK (BATCH*SEQ)   /* 4096 */

#define QT 64
#define KT 64
#define FLASH_SMEM ((3*QT*HD + QT*KT + 3*QT)*4)

// Scratch (device globals; no runtime allocation)
__device__ float g_xn[(size_t)TOK * DIM];
__device__ float g_qkv[(size_t)TOK * QKV_DIM];
__device__ float g_attn[(size_t)TOK * DIM];

// ---------------------------------------------------------------------------
// RMSNorm
// ---------------------------------------------------------------------------
__global__ __launch_bounds__(256) void rmsnorm_kernel(const float* __restrict__ x,
                                                      const float* __restrict__ w,
                                                      float* __restrict__ out) {
    int row = blockIdx.x;
    int t = threadIdx.x;
    const float4* xr = (const float4*)(x + (size_t)row * DIM);
    float4 v[2];
    float s = 0.f;
#pragma unroll
    for (int i = 0; i < 2; i++) {
        v[i] = xr[t + i * 256];
        s += v[i].x * v[i].x + v[i].y * v[i].y + v[i].z * v[i].z + v[i].w * v[i].w;
    }
    __shared__ float red[8];
#pragma unroll
    for (int o = 16; o > 0; o >>= 1) s += __shfl_xor_sync(~0u, s, o);
    if ((t & 31) == 0) red[t >> 5] = s;
    __syncthreads();
    if (t < 32) {
        float ss = (t < 8) ? red[t] : 0.f;
#pragma unroll
        for (int o = 4; o > 0; o >>= 1) ss += __shfl_xor_sync(~0u, ss, o);
        if (t == 0) red[0] = rsqrtf(ss / (float)DIM + 1e-6f);
    }
    __syncthreads();
    float rs = red[0];
    float4* o4 = (float4*)(out + (size_t)row * DIM);
    const float4* w4 = (const float4*)w;
#pragma unroll
    for (int i = 0; i < 2; i++) {
        float4 wv = w4[t + i * 256];
        float4 r;
        r.x = v[i].x * rs * wv.x;
        r.y = v[i].y * rs * wv.y;
        r.z = v[i].z * rs * wv.z;
        r.w = v[i].w * rs * wv.w;
        o4[t + i * 256] = r;
    }
}

// ---------------------------------------------------------------------------
// TF32 tensor-core NT GEMM: C[m][n] = sum_k A[m][k]*B[n][k]
// Block 128x128x32, 8 warps, warp tile 32x64 (2x8 m16n8k8 frags).
// fp32->tf32 (rna) during staging into fragment-order smem.
// Double-buffered smem (64KB) + register prefetch.
// ---------------------------------------------------------------------------
#define TBM 128
#define TBN 128
#define TBK 32
#define GEMM_SMEM (2 * (TBM*TBK + TBN*TBK) * 4)  /* 64KB */

__device__ __forceinline__ uint32_t f2tf(float f) {
    uint32_t u;
    asm("cvt.rna.tf32.f32 %0, %1;" : "=r"(u) : "f"(f));
    return u;
}

__device__ __forceinline__ void mma_tf32(float* c, const uint32_t* a, const uint32_t* b) {
    asm volatile(
        "mma.sync.aligned.m16n8k8.row.col.f32.tf32.tf32.f32 "
        "{%0,%1,%2,%3}, {%4,%5,%6,%7}, {%8,%9}, {%0,%1,%2,%3};"
        : "+f"(c[0]), "+f"(c[1]), "+f"(c[2]), "+f"(c[3])
        : "r"(a[0]), "r"(a[1]), "r"(a[2]), "r"(a[3]), "r"(b[0]), "r"(b[1]));
}

__global__ __launch_bounds__(256) void gemm_nt_tf32(const float* __restrict__ A,
                                                    const float* __restrict__ B,
                                                    float* __restrict__ C,
                                                    int M, int N, int K) {
    extern __shared__ uint32_t sm[];
    uint32_t* As = sm;                          // [2][TBM*TBK] frag-order
    uint32_t* Bs = sm + 2 * TBM * TBK;          // [2][TBN*TBK] frag-order

    int t = threadIdx.x;
    int lane = t & 31, w = t >> 5;
    int wr = w & 3, wc = w >> 2;                // warp row (x32), warp col (x64)
    int m0 = blockIdx.y * TBM, n0 = blockIdx.x * TBN;

    float acc[2][8][4];
#pragma unroll
    for (int i = 0; i < 2; i++)
#pragma unroll
        for (int j = 0; j < 8; j++)
#pragma unroll
            for (int e = 0; e < 4; e++) acc[i][j][e] = 0.f;

    // per-thread gmem load coordinates: id = t + i*256; row = id>>3; q = id&7 (float4 group)
    float4 Ar[4], Br[4];

#define LOAD_TILES(k0)                                                          \
    _Pragma("unroll")                                                           \
    for (int i = 0; i < 4; i++) {                                               \
        int id = t + i * 256;                                                   \
        int r = id >> 3, q = id & 7;                                            \
        Ar[i] = *(const float4*)(A + (size_t)(m0 + r) * K + (k0) + 4 * q);      \
        Br[i] = *(const float4*)(B + (size_t)(n0 + r) * K + (k0) + 4 * q);      \
    }

#define STORE_TILES(buf)                                                        \
    _Pragma("unroll")                                                           \
    for (int i = 0; i < 4; i++) {                                               \
        int id = t + i * 256;                                                   \
        int r = id >> 3, q = id & 7;                                            \
        /* A: frag = (r>>4)*4 + (q>>1); j = (r16>>3) + 2*(q&1); lane=(r16&7)*4+e */ \
        int r16 = r & 15;                                                       \
        int fa = (r >> 4) * 4 + (q >> 1);                                       \
        int ja = (r16 >> 3) + 2 * (q & 1);                                      \
        uint32_t* ab = &As[(buf) * (TBM * TBK) + fa * 128 + (r16 & 7) * 16 + ja]; \
        ab[0]  = f2tf(Ar[i].x);                                                 \
        ab[4]  = f2tf(Ar[i].y);                                                 \
        ab[8]  = f2tf(Ar[i].z);                                                 \
        ab[12] = f2tf(Ar[i].w);                                                 \
        /* B: frag = (n>>3)*4 + (q>>1); j = q&1; lane = (n&7)*4+e */            \
        int n8 = r & 7;                                                         \
        int fb = (r >> 3) * 4 + (q >> 1);                                       \
        uint32_t* bb = &Bs[(buf) * (TBN * TBK) + fb * 64 + n8 * 8 + (q & 1)];   \
        bb[0] = f2tf(Br[i].x);                                                  \
        bb[2] = f2tf(Br[i].y);                                                  \
        bb[4] = f2tf(Br[i].z);                                                  \
        bb[6] = f2tf(Br[i].w);                                                  \
    }

    LOAD_TILES(0);
    STORE_TILES(0);
    __syncthreads();

    int buf = 0;
    for (int k0 = 0; k0 < K; k0 += TBK) {
        bool has_next = (k0 + TBK) < K;
        if (has_next) { LOAD_TILES(k0 + TBK); }

        // compute on buf: 4 k-steps of 8
#pragma unroll
        for (int kt = 0; kt < 4; kt++) {
            uint32_t af[2][4], bf[8][2];
#pragma unroll
            for (int i = 0; i < 2; i++) {
                int mt = wr * 2 + i;
                const uint4 v = *(const uint4*)&As[buf * (TBM * TBK) + (mt * 4 + kt) * 128 + lane * 4];
                af[i][0] = v.x; af[i][1] = v.y; af[i][2] = v.z; af[i][3] = v.w;
            }
#pragma unroll
            for (int j = 0; j < 8; j++) {
                int nt = wc * 8 + j;
                const uint2 v = *(const uint2*)&Bs[buf * (TBN * TBK) + (nt * 4 + kt) * 64 + lane * 2];
                bf[j][0] = v.x; bf[j][1] = v.y;
            }
#pragma unroll
            for (int i = 0; i < 2; i++)
#pragma unroll
                for (int j = 0; j < 8; j++)
                    mma_tf32(acc[i][j], af[i], bf[j]);
        }

        if (has_next) { STORE_TILES(buf ^ 1); }
        __syncthreads();
        buf ^= 1;
    }

    // epilogue: frag (i,j): rows m0 + (wr*2+i)*16 + (lane>>2) (+8), cols n0+(wc*8+j)*8 + 2*(lane&3)
#pragma unroll
    for (int i = 0; i < 2; i++) {
#pragma unroll
        for (int j = 0; j < 8; j++) {
            int row = m0 + (wr * 2 + i) * 16 + (lane >> 2);
            int col = n0 + (wc * 8 + j) * 8 + 2 * (lane & 3);
            *(float2*)&C[(size_t)row * N + col] = make_float2(acc[i][j][0], acc[i][j][1]);
            *(float2*)&C[(size_t)(row + 8) * N + col] = make_float2(acc[i][j][2], acc[i][j][3]);
        }
    }
}

// ---------------------------------------------------------------------------
// RoPE in-place on q and k portions of qkv.
// ---------------------------------------------------------------------------
__global__ __launch_bounds__(256) void rope_kernel(float* __restrict__ qkv,
                                                   const float* __restrict__ freqs) {
    int tok = blockIdx.x;
    int s = tok % SEQ;
    for (int idx = threadIdx.x; idx < (NH + NKV) * (HD / 2); idx += blockDim.x) {
        int head = idx >> 6;
        int p = idx & 63;
        float* ptr;
        if (head < NH)
            ptr = qkv + (size_t)tok * QKV_DIM + head * HD;
        else
            ptr = qkv + (size_t)tok * QKV_DIM + NH * HD + (head - NH) * HD;
        float c  = freqs[(s * 64 + p) * 2 + 0];
        float sn = freqs[(s * 64 + p) * 2 + 1];
        float xr = ptr[2 * p];
        float xi = ptr[2 * p + 1];
        ptr[2 * p]     = xr * c - xi * sn;
        ptr[2 * p + 1] = xr * sn + xi * c;
    }
}

// ---------------------------------------------------------------------------
// Flash attention (causal, GQA) — unchanged fp32 this round.
// ---------------------------------------------------------------------------
__global__ __launch_bounds__(256) void flash_kernel(const float* __restrict__ qkv,
                                                    float* __restrict__ attn) {
    extern __shared__ float smf[];
    float* Qs = smf;
    float* Ks = Qs + QT * HD;
    float* Vs = Ks + KT * HD;
    float* Ss = Vs + KT * HD;
    float* mrow = Ss + QT * KT;
    float* lrow = mrow + QT;
    float* arow = lrow + QT;

    int qt = gridDim.x - 1 - blockIdx.x;
    int h = blockIdx.y;
    int b = blockIdx.z;
    int kvh = h / (NH / NKV);
    int t = threadIdx.x;
    int lane = t & 31, w = t >> 5;
    int q0 = qt * QT;

    const float* qbase = qkv + (size_t)b * SEQ * QKV_DIM + (size_t)h * HD;
    const float* kbase = qkv + (size_t)b * SEQ * QKV_DIM + NH * HD + (size_t)kvh * HD;
    const float* vbase = kbase + NKV * HD;

    for (int i = t; i < QT * (HD / 4); i += 256) {
        int r = i / (HD / 4), c4 = i % (HD / 4);
        *(float4*)&Qs[r * HD + 4 * c4] =
            *(const float4*)&qbase[(size_t)(q0 + r) * QKV_DIM + 4 * c4];
    }
    if (t < QT) { mrow[t] = -1e30f; lrow[t] = 0.f; }

    float acc[8][4] = {};
    const float scale = 0.08838834764831845f;

    for (int kt = 0; kt <= qt; kt++) {
        int k0 = kt * KT;
        __syncthreads();
        for (int i = t; i < KT * (HD / 4); i += 256) {
            int r = i / (HD / 4), c4 = i % (HD / 4);
            *(float4*)&Ks[r * HD + 4 * c4] =
                *(const float4*)&kbase[(size_t)(k0 + r) * QKV_DIM + 4 * c4];
            *(float4*)&Vs[r * HD + 4 * c4] =
                *(const float4*)&vbase[(size_t)(k0 + r) * QKV_DIM + 4 * c4];
        }
        __syncthreads();

        {
            int ti = t & 15, tj = t >> 4;
            int r0 = 4 * tj, c0 = 4 * ti;
            float s4[4][4] = {};
#pragma unroll 4
            for (int kk = 0; kk < HD / 4; kk++) {
                float4 q4[4], k4[4];
#pragma unroll
                for (int i = 0; i < 4; i++) q4[i] = *(const float4*)&Qs[(r0 + i) * HD + 4 * kk];
#pragma unroll
                for (int j = 0; j < 4; j++) k4[j] = *(const float4*)&Ks[(c0 + j) * HD + 4 * kk];
#pragma unroll
                for (int i = 0; i < 4; i++)
#pragma unroll
                    for (int j = 0; j < 4; j++)
                        s4[i][j] += q4[i].x * k4[j].x + q4[i].y * k4[j].y +
                                    q4[i].z * k4[j].z + q4[i].w * k4[j].w;
            }
#pragma unroll
            for (int i = 0; i < 4; i++)
#pragma unroll
                for (int j = 0; j < 4; j++) {
                    float v = s4[i][j] * scale;
                    if (k0 + c0 + j > q0 + r0 + i) v = -1e30f;
                    Ss[(r0 + i) * KT + c0 + j] = v;
                }
        }
        __syncthreads();

        if (t < QT) {
            int r = t;
            float mold = mrow[r];
            float mnew = mold;
#pragma unroll 8
            for (int j = 0; j < KT; j++) mnew = fmaxf(mnew, Ss[r * KT + j]);
            float alpha = __expf(mold - mnew);
            float rs = 0.f;
#pragma unroll 8
            for (int j = 0; j < KT; j++) {
                float p = __expf(Ss[r * KT + j] - mnew);
                Ss[r * KT + j] = p;
                rs += p;
            }
            lrow[r] = lrow[r] * alpha + rs;
            mrow[r] = mnew;
            arow[r] = alpha;
        }
        __syncthreads();

        {
            int c0 = 4 * lane;
#pragma unroll
            for (int i = 0; i < 8; i++) {
                float a = arow[8 * w + i];
#pragma unroll
                for (int j = 0; j < 4; j++) acc[i][j] *= a;
            }
            for (int j = 0; j < KT; j++) {
                float4 v4 = *(const float4*)&Vs[j * HD + c0];
#pragma unroll
                for (int i = 0; i < 8; i++) {
                    float p = Ss[(8 * w + i) * KT + j];
                    acc[i][0] += p * v4.x;
                    acc[i][1] += p * v4.y;
                    acc[i][2] += p * v4.z;
                    acc[i][3] += p * v4.w;
                }
            }
        }
    }

    {
        int c0 = 4 * lane;
#pragma unroll
        for (int i = 0; i < 8; i++) {
            int r = 8 * w + i;
            float inv = 1.f / lrow[r];
            float4 o;
            o.x = acc[i][0] * inv;
            o.y = acc[i][1] * inv;
            o.z = acc[i][2] * inv;
            o.w = acc[i][3] * inv;
            *(float4*)&attn[(size_t)(b * SEQ + q0 + r) * DIM + h * HD + c0] = o;
        }
    }
}

// ---------------------------------------------------------------------------
extern "C" void kernel_launch(void* const* d_in, const int* in_sizes, int n_in,
                              void* d_out, int out_size) {
    (void)in_sizes; (void)n_in; (void)out_size;
    const float* x      = (const float*)d_in[0];
    const float* freqs  = (const float*)d_in[1];
    const float* norm_w = (const float*)d_in[2];
    const float* wqkv   = (const float*)d_in[3];
    const float* wo     = (const float*)d_in[4];
    float* out = (float*)d_out;

    float *xn, *qkv, *attn;
    cudaGetSymbolAddress((void**)&xn, g_xn);
    cudaGetSymbolAddress((void**)&qkv, g_qkv);
    cudaGetSymbolAddress((void**)&attn, g_attn);

    rmsnorm_kernel<<<TOK, 256>>>(x, norm_w, xn);

    cudaFuncSetAttribute(gemm_nt_tf32, cudaFuncAttributeMaxDynamicSharedMemorySize, GEMM_SMEM);
    gemm_nt_tf32<<<dim3(QKV_DIM / TBN, TOK / TBM), 256, GEMM_SMEM>>>(xn, wqkv, qkv, TOK, QKV_DIM, DIM);

    rope_kernel<<<TOK, 256>>>(qkv, freqs);

    cudaFuncSetAttribute(flash_kernel, cudaFuncAttributeMaxDynamicSharedMemorySize, FLASH_SMEM);
    flash_kernel<<<dim3(SEQ / QT, NH, BATCH), 256, FLASH_SMEM>>>(qkv, attn);

    gemm_nt_tf32<<<dim3(DIM / TBN, TOK / TBM), 256, GEMM_SMEM>>>(attn, wo, out, TOK, DIM, DIM);
}

// round 4
// speedup vs baseline: 2.9245x; 2.2207x over previous
#include <cuda_runtime.h>
#include <math.h>
#include <stdint.h>

#define BATCH 2
#define SEQ 2048
#define DIM 2048
#define NH 16
#define NKV 4
#define HD 128
#define QKV_DIM 3072      /* (16 + 2*4) * 128 */
#define TOK (BATCH*SEQ)   /* 4096 */

// Scratch (device globals; no runtime allocation)
__device__ float g_xn[(size_t)TOK * DIM];
__device__ float g_qkv[(size_t)TOK * QKV_DIM];
__device__ float g_attn[(size_t)TOK * DIM];

__device__ __forceinline__ uint32_t f2tf(float f) {
    uint32_t u;
    asm("cvt.rna.tf32.f32 %0, %1;" : "=r"(u) : "f"(f));
    return u;
}

__device__ __forceinline__ void mma_tf32(float* c, const uint32_t* a, const uint32_t* b) {
    asm volatile(
        "mma.sync.aligned.m16n8k8.row.col.f32.tf32.tf32.f32 "
        "{%0,%1,%2,%3}, {%4,%5,%6,%7}, {%8,%9}, {%0,%1,%2,%3};"
        : "+f"(c[0]), "+f"(c[1]), "+f"(c[2]), "+f"(c[3])
        : "r"(a[0]), "r"(a[1]), "r"(a[2]), "r"(a[3]), "r"(b[0]), "r"(b[1]));
}

// ---------------------------------------------------------------------------
// RMSNorm
// ---------------------------------------------------------------------------
__global__ __launch_bounds__(256) void rmsnorm_kernel(const float* __restrict__ x,
                                                      const float* __restrict__ w,
                                                      float* __restrict__ out) {
    int row = blockIdx.x;
    int t = threadIdx.x;
    const float4* xr = (const float4*)(x + (size_t)row * DIM);
    float4 v[2];
    float s = 0.f;
#pragma unroll
    for (int i = 0; i < 2; i++) {
        v[i] = xr[t + i * 256];
        s += v[i].x * v[i].x + v[i].y * v[i].y + v[i].z * v[i].z + v[i].w * v[i].w;
    }
    __shared__ float red[8];
#pragma unroll
    for (int o = 16; o > 0; o >>= 1) s += __shfl_xor_sync(~0u, s, o);
    if ((t & 31) == 0) red[t >> 5] = s;
    __syncthreads();
    if (t < 32) {
        float ss = (t < 8) ? red[t] : 0.f;
#pragma unroll
        for (int o = 4; o > 0; o >>= 1) ss += __shfl_xor_sync(~0u, ss, o);
        if (t == 0) red[0] = rsqrtf(ss / (float)DIM + 1e-6f);
    }
    __syncthreads();
    float rs = red[0];
    float4* o4 = (float4*)(out + (size_t)row * DIM);
    const float4* w4 = (const float4*)w;
#pragma unroll
    for (int i = 0; i < 2; i++) {
        float4 wv = w4[t + i * 256];
        float4 r;
        r.x = v[i].x * rs * wv.x;
        r.y = v[i].y * rs * wv.y;
        r.z = v[i].z * rs * wv.z;
        r.w = v[i].w * rs * wv.w;
        o4[t + i * 256] = r;
    }
}

// ---------------------------------------------------------------------------
// TF32 tensor-core NT GEMM (verified R2): C[m][n] = sum_k A[m][k]*B[n][k]
// ---------------------------------------------------------------------------
#define TBM 128
#define TBN 128
#define TBK 32
#define GEMM_SMEM (2 * (TBM*TBK + TBN*TBK) * 4)  /* 64KB */

__global__ __launch_bounds__(256) void gemm_nt_tf32(const float* __restrict__ A,
                                                    const float* __restrict__ B,
                                                    float* __restrict__ C,
                                                    int M, int N, int K) {
    extern __shared__ uint32_t sm[];
    uint32_t* As = sm;
    uint32_t* Bs = sm + 2 * TBM * TBK;

    int t = threadIdx.x;
    int lane = t & 31, w = t >> 5;
    int wr = w & 3, wc = w >> 2;
    int m0 = blockIdx.y * TBM, n0 = blockIdx.x * TBN;

    float acc[2][8][4];
#pragma unroll
    for (int i = 0; i < 2; i++)
#pragma unroll
        for (int j = 0; j < 8; j++)
#pragma unroll
            for (int e = 0; e < 4; e++) acc[i][j][e] = 0.f;

    float4 Ar[4], Br[4];

#define LOAD_TILES(k0)                                                          \
    _Pragma("unroll")                                                           \
    for (int i = 0; i < 4; i++) {                                               \
        int id = t + i * 256;                                                   \
        int r = id >> 3, q = id & 7;                                            \
        Ar[i] = *(const float4*)(A + (size_t)(m0 + r) * K + (k0) + 4 * q);      \
        Br[i] = *(const float4*)(B + (size_t)(n0 + r) * K + (k0) + 4 * q);      \
    }

#define STORE_TILES(buf)                                                        \
    _Pragma("unroll")                                                           \
    for (int i = 0; i < 4; i++) {                                               \
        int id = t + i * 256;                                                   \
        int r = id >> 3, q = id & 7;                                            \
        int r16 = r & 15;                                                       \
        int fa = (r >> 4) * 4 + (q >> 1);                                       \
        int ja = (r16 >> 3) + 2 * (q & 1);                                      \
        uint32_t* ab = &As[(buf) * (TBM * TBK) + fa * 128 + (r16 & 7) * 16 + ja]; \
        ab[0]  = f2tf(Ar[i].x);                                                 \
        ab[4]  = f2tf(Ar[i].y);                                                 \
        ab[8]  = f2tf(Ar[i].z);                                                 \
        ab[12] = f2tf(Ar[i].w);                                                 \
        int n8 = r & 7;                                                         \
        int fb = (r >> 3) * 4 + (q >> 1);                                       \
        uint32_t* bb = &Bs[(buf) * (TBN * TBK) + fb * 64 + n8 * 8 + (q & 1)];   \
        bb[0] = f2tf(Br[i].x);                                                  \
        bb[2] = f2tf(Br[i].y);                                                  \
        bb[4] = f2tf(Br[i].z);                                                  \
        bb[6] = f2tf(Br[i].w);                                                  \
    }

    LOAD_TILES(0);
    STORE_TILES(0);
    __syncthreads();

    int buf = 0;
    for (int k0 = 0; k0 < K; k0 += TBK) {
        bool has_next = (k0 + TBK) < K;
        if (has_next) { LOAD_TILES(k0 + TBK); }

#pragma unroll
        for (int kt = 0; kt < 4; kt++) {
            uint32_t af[2][4], bf[8][2];
#pragma unroll
            for (int i = 0; i < 2; i++) {
                int mt = wr * 2 + i;
                const uint4 v = *(const uint4*)&As[buf * (TBM * TBK) + (mt * 4 + kt) * 128 + lane * 4];
                af[i][0] = v.x; af[i][1] = v.y; af[i][2] = v.z; af[i][3] = v.w;
            }
#pragma unroll
            for (int j = 0; j < 8; j++) {
                int nt = wc * 8 + j;
                const uint2 v = *(const uint2*)&Bs[buf * (TBN * TBK) + (nt * 4 + kt) * 64 + lane * 2];
                bf[j][0] = v.x; bf[j][1] = v.y;
            }
#pragma unroll
            for (int i = 0; i < 2; i++)
#pragma unroll
                for (int j = 0; j < 8; j++)
                    mma_tf32(acc[i][j], af[i], bf[j]);
        }

        if (has_next) { STORE_TILES(buf ^ 1); }
        __syncthreads();
        buf ^= 1;
    }

#pragma unroll
    for (int i = 0; i < 2; i++) {
#pragma unroll
        for (int j = 0; j < 8; j++) {
            int row = m0 + (wr * 2 + i) * 16 + (lane >> 2);
            int col = n0 + (wc * 8 + j) * 8 + 2 * (lane & 3);
            *(float2*)&C[(size_t)row * N + col] = make_float2(acc[i][j][0], acc[i][j][1]);
            *(float2*)&C[(size_t)(row + 8) * N + col] = make_float2(acc[i][j][2], acc[i][j][3]);
        }
    }
}

// ---------------------------------------------------------------------------
// RoPE in-place on q and k portions of qkv.
// ---------------------------------------------------------------------------
__global__ __launch_bounds__(256) void rope_kernel(float* __restrict__ qkv,
                                                   const float* __restrict__ freqs) {
    int tok = blockIdx.x;
    int s = tok % SEQ;
    for (int idx = threadIdx.x; idx < (NH + NKV) * (HD / 2); idx += blockDim.x) {
        int head = idx >> 6;
        int p = idx & 63;
        float* ptr;
        if (head < NH)
            ptr = qkv + (size_t)tok * QKV_DIM + head * HD;
        else
            ptr = qkv + (size_t)tok * QKV_DIM + NH * HD + (head - NH) * HD;
        float c  = freqs[(s * 64 + p) * 2 + 0];
        float sn = freqs[(s * 64 + p) * 2 + 1];
        float xr = ptr[2 * p];
        float xi = ptr[2 * p + 1];
        ptr[2 * p]     = xr * c - xi * sn;
        ptr[2 * p + 1] = xr * sn + xi * c;
    }
}

// ---------------------------------------------------------------------------
// Tensor-core flash attention (causal, GQA), tf32 mma.sync.
// CTA: 128 q-rows, 8 warps (warp w owns rows w*16..w*16+15). KV tiles of 64.
// Q staged as A-frags, K as B-frags (S = Q K^T), V as B-frags (O += P V).
// Softmax fully in registers (quad shuffles). P round-trips via padded smem.
// ---------------------------------------------------------------------------
#define FQT 128
#define FKT 64
#define PSTR 72
// u32 offsets into dynamic smem
#define QS_OFF 0                 /* 8 mtiles * 16 kc * 128 = 16384 */
#define KS_OFF 16384             /* 8 ntiles * 16 kc * 64  = 8192 */
#define VS_OFF (16384 + 8192)    /* 16 ntiles * 8 kc * 64  = 8192 */
#define PS_OFF (16384 + 8192 + 8192)  /* 128 * 72 = 9216 */
#define FLASH_SMEM ((16384 + 8192 + 8192 + 9216) * 4)  /* 167936 B */

__global__ __launch_bounds__(256) void flash_tc(const float* __restrict__ qkv,
                                                float* __restrict__ attn) {
    extern __shared__ uint32_t sm[];
    uint32_t* Qs = sm + QS_OFF;
    uint32_t* Ks = sm + KS_OFF;
    uint32_t* Vs = sm + VS_OFF;
    uint32_t* Ps = sm + PS_OFF;

    int bqt = gridDim.x - 1 - blockIdx.x;   // heavy tiles first
    int h = blockIdx.y, b = blockIdx.z;
    int kvh = h >> 2;                       // NH/NKV = 4
    int t = threadIdx.x, lane = t & 31, w = t >> 5;
    int q0 = bqt * FQT;

    const float* qbase = qkv + (size_t)b * SEQ * QKV_DIM + h * HD;
    const float* kbase = qkv + (size_t)b * SEQ * QKV_DIM + NH * HD + kvh * HD;
    const float* vbase = kbase + NKV * HD;

    // Stage Q tile (128x128) into A-frag order, tf32.
#pragma unroll
    for (int i = 0; i < 16; i++) {
        int id = t + i * 256;
        int r = id >> 5, q = id & 31;
        float4 v = *(const float4*)(qbase + (size_t)(q0 + r) * QKV_DIM + 4 * q);
        int r16 = r & 15;
        uint32_t* p = &Qs[((r >> 4) * 16 + (q >> 1)) * 128 + (r16 & 7) * 16 + (r16 >> 3) + 2 * (q & 1)];
        p[0]  = f2tf(v.x);
        p[4]  = f2tf(v.y);
        p[8]  = f2tf(v.z);
        p[12] = f2tf(v.w);
    }

    float m0 = -1e30f, m1 = -1e30f, l0 = 0.f, l1 = 0.f;
    float O[16][4];
#pragma unroll
    for (int nt = 0; nt < 16; nt++)
#pragma unroll
        for (int e = 0; e < 4; e++) O[nt][e] = 0.f;

    const float scale = 0.08838834764831845f;  // 1/sqrt(128)
    int g = lane >> 2;
    int row0 = q0 + w * 16 + g;
    int ntiles = 2 * bqt + 2;

    for (int kt = 0; kt < ntiles; kt++) {
        int k0 = kt * FKT;
        __syncthreads();   // prior readers of Ks/Vs done (also covers Q staging iter 0)

        // Stage K tile (64x128) as B-frags, V tile (64x128) as B-frags for PV.
#pragma unroll
        for (int i = 0; i < 8; i++) {
            int id = t + i * 256;
            int r = id >> 5, q = id & 31;       // r = kv row, q = float4 group
            float4 kv4 = *(const float4*)(kbase + (size_t)(k0 + r) * QKV_DIM + 4 * q);
            uint32_t* kp = &Ks[((r >> 3) * 16 + (q >> 1)) * 64 + (r & 7) * 8 + (q & 1)];
            kp[0] = f2tf(kv4.x);
            kp[2] = f2tf(kv4.y);
            kp[4] = f2tf(kv4.z);
            kp[6] = f2tf(kv4.w);
            float4 vv = *(const float4*)(vbase + (size_t)(k0 + r) * QKV_DIM + 4 * q);
            // V[r][4q+e]: ntile=q>>1, n8=4*(q&1)+e, kc=r>>3, kw=r&7 -> reg=kw>>2, lane=n8*4+(kw&3)
            uint32_t* vp = &Vs[((q >> 1) * 8 + (r >> 3)) * 64 + (16 * (q & 1) + (r & 3)) * 2 + ((r >> 2) & 1)];
            vp[0]  = f2tf(vv.x);
            vp[8]  = f2tf(vv.y);
            vp[16] = f2tf(vv.z);
            vp[24] = f2tf(vv.w);
        }
        __syncthreads();

        // S = Q K^T for this warp's 16 rows x 64 cols
        float sacc[8][4];
#pragma unroll
        for (int j = 0; j < 8; j++)
#pragma unroll
            for (int e = 0; e < 4; e++) sacc[j][e] = 0.f;

#pragma unroll
        for (int kc = 0; kc < 16; kc++) {
            uint32_t a[4];
            *(uint4*)a = *(const uint4*)&Qs[(w * 16 + kc) * 128 + lane * 4];
#pragma unroll
            for (int j = 0; j < 8; j++) {
                uint32_t bf[2];
                *(uint2*)bf = *(const uint2*)&Ks[(j * 16 + kc) * 64 + lane * 2];
                mma_tf32(sacc[j], a, bf);
            }
        }

        // scale + causal mask
#pragma unroll
        for (int j = 0; j < 8; j++)
#pragma unroll
            for (int e = 0; e < 4; e++) sacc[j][e] *= scale;

        if (k0 + FKT - 1 > row0) {
            int colb = k0 + 2 * (lane & 3);
#pragma unroll
            for (int j = 0; j < 8; j++) {
                int c = colb + j * 8;
                if (c > row0)     sacc[j][0] = -1e30f;
                if (c + 1 > row0) sacc[j][1] = -1e30f;
                if (c > row0 + 8)     sacc[j][2] = -1e30f;
                if (c + 1 > row0 + 8) sacc[j][3] = -1e30f;
            }
        }

        // register softmax (row = quad; shfl over lane&3)
        float mx0 = -1e30f, mx1 = -1e30f;
#pragma unroll
        for (int j = 0; j < 8; j++) {
            mx0 = fmaxf(mx0, fmaxf(sacc[j][0], sacc[j][1]));
            mx1 = fmaxf(mx1, fmaxf(sacc[j][2], sacc[j][3]));
        }
        mx0 = fmaxf(mx0, __shfl_xor_sync(~0u, mx0, 1));
        mx0 = fmaxf(mx0, __shfl_xor_sync(~0u, mx0, 2));
        mx1 = fmaxf(mx1, __shfl_xor_sync(~0u, mx1, 1));
        mx1 = fmaxf(mx1, __shfl_xor_sync(~0u, mx1, 2));
        float mn0 = fmaxf(m0, mx0), mn1 = fmaxf(m1, mx1);
        float al0 = __expf(m0 - mn0), al1 = __expf(m1 - mn1);
        m0 = mn0; m1 = mn1;

        float s0 = 0.f, s1 = 0.f;
        uint32_t* prow = &Ps[(w * 16 + g) * PSTR + 2 * (lane & 3)];
#pragma unroll
        for (int j = 0; j < 8; j++) {
            float p0 = __expf(sacc[j][0] - mn0);
            float p1 = __expf(sacc[j][1] - mn0);
            float p2 = __expf(sacc[j][2] - mn1);
            float p3 = __expf(sacc[j][3] - mn1);
            s0 += p0 + p1;
            s1 += p2 + p3;
            prow[j * 8]     = f2tf(p0);
            prow[j * 8 + 1] = f2tf(p1);
            prow[8 * PSTR + j * 8]     = f2tf(p2);
            prow[8 * PSTR + j * 8 + 1] = f2tf(p3);
        }
        s0 += __shfl_xor_sync(~0u, s0, 1);
        s0 += __shfl_xor_sync(~0u, s0, 2);
        s1 += __shfl_xor_sync(~0u, s1, 1);
        s1 += __shfl_xor_sync(~0u, s1, 2);
        l0 = l0 * al0 + s0;
        l1 = l1 * al1 + s1;

        // rescale O
#pragma unroll
        for (int nt = 0; nt < 16; nt++) {
            O[nt][0] *= al0; O[nt][1] *= al0;
            O[nt][2] *= al1; O[nt][3] *= al1;
        }
        __syncwarp();   // P rows warp-private: make cross-lane stores visible

        // O += P V
#pragma unroll
        for (int kc = 0; kc < 8; kc++) {
            uint32_t a[4];
            const uint32_t* pb = &Ps[(w * 16 + g) * PSTR + kc * 8 + (lane & 3)];
            a[0] = pb[0];
            a[2] = pb[4];
            a[1] = pb[8 * PSTR];
            a[3] = pb[8 * PSTR + 4];
#pragma unroll
            for (int nt = 0; nt < 16; nt++) {
                uint32_t bf[2];
                *(uint2*)bf = *(const uint2*)&Vs[(nt * 8 + kc) * 64 + lane * 2];
                mma_tf32(O[nt], a, bf);
            }
        }
        __syncwarp();   // PV reads done before next tile's P stores
    }

    // epilogue
    float inv0 = 1.f / l0, inv1 = 1.f / l1;
    float* ob  = attn + ((size_t)(b * SEQ) + row0) * DIM + h * HD;
    float* ob8 = ob + 8 * DIM;
#pragma unroll
    for (int nt = 0; nt < 16; nt++) {
        int c = nt * 8 + 2 * (lane & 3);
        *(float2*)(ob + c)  = make_float2(O[nt][0] * inv0, O[nt][1] * inv0);
        *(float2*)(ob8 + c) = make_float2(O[nt][2] * inv1, O[nt][3] * inv1);
    }
}

// ---------------------------------------------------------------------------
extern "C" void kernel_launch(void* const* d_in, const int* in_sizes, int n_in,
                              void* d_out, int out_size) {
    (void)in_sizes; (void)n_in; (void)out_size;
    const float* x      = (const float*)d_in[0];
    const float* freqs  = (const float*)d_in[1];
    const float* norm_w = (const float*)d_in[2];
    const float* wqkv   = (const float*)d_in[3];
    const float* wo     = (const float*)d_in[4];
    float* out = (float*)d_out;

    float *xn, *qkv, *attn;
    cudaGetSymbolAddress((void**)&xn, g_xn);
    cudaGetSymbolAddress((void**)&qkv, g_qkv);
    cudaGetSymbolAddress((void**)&attn, g_attn);

    rmsnorm_kernel<<<TOK, 256>>>(x, norm_w, xn);

    cudaFuncSetAttribute(gemm_nt_tf32, cudaFuncAttributeMaxDynamicSharedMemorySize, GEMM_SMEM);
    gemm_nt_tf32<<<dim3(QKV_DIM / TBN, TOK / TBM), 256, GEMM_SMEM>>>(xn, wqkv, qkv, TOK, QKV_DIM, DIM);

    rope_kernel<<<TOK, 256>>>(qkv, freqs);

    cudaFuncSetAttribute(flash_tc, cudaFuncAttributeMaxDynamicSharedMemorySize, FLASH_SMEM);
    flash_tc<<<dim3(SEQ / FQT, NH, BATCH), 256, FLASH_SMEM>>>(qkv, attn);

    gemm_nt_tf32<<<dim3(DIM / TBN, TOK / TBM), 256, GEMM_SMEM>>>(attn, wo, out, TOK, DIM, DIM);
}

// round 5
// speedup vs baseline: 2.9746x; 1.0171x over previous
#include <cuda_runtime.h>
#include <math.h>
#include <stdint.h>

#define BATCH 2
#define SEQ 2048
#define DIM 2048
#define NH 16
#define NKV 4
#define HD 128
#define QKV_DIM 3072      /* (16 + 2*4) * 128 */
#define TOK (BATCH*SEQ)   /* 4096 */

// Scratch (device globals; no runtime allocation)
__device__ float g_xn[(size_t)TOK * DIM];
__device__ float g_qkv[(size_t)TOK * QKV_DIM];
__device__ float g_attn[(size_t)TOK * DIM];

__device__ __forceinline__ uint32_t f2tf(float f) {
    uint32_t u;
    asm("cvt.rna.tf32.f32 %0, %1;" : "=r"(u) : "f"(f));
    return u;
}

__device__ __forceinline__ void mma_tf32(float* c, const uint32_t* a, const uint32_t* b) {
    asm volatile(
        "mma.sync.aligned.m16n8k8.row.col.f32.tf32.tf32.f32 "
        "{%0,%1,%2,%3}, {%4,%5,%6,%7}, {%8,%9}, {%0,%1,%2,%3};"
        : "+f"(c[0]), "+f"(c[1]), "+f"(c[2]), "+f"(c[3])
        : "r"(a[0]), "r"(a[1]), "r"(a[2]), "r"(a[3]), "r"(b[0]), "r"(b[1]));
}

// ---------------------------------------------------------------------------
// RMSNorm
// ---------------------------------------------------------------------------
__global__ __launch_bounds__(256) void rmsnorm_kernel(const float* __restrict__ x,
                                                      const float* __restrict__ w,
                                                      float* __restrict__ out) {
    int row = blockIdx.x;
    int t = threadIdx.x;
    const float4* xr = (const float4*)(x + (size_t)row * DIM);
    float4 v[2];
    float s = 0.f;
#pragma unroll
    for (int i = 0; i < 2; i++) {
        v[i] = xr[t + i * 256];
        s += v[i].x * v[i].x + v[i].y * v[i].y + v[i].z * v[i].z + v[i].w * v[i].w;
    }
    __shared__ float red[8];
#pragma unroll
    for (int o = 16; o > 0; o >>= 1) s += __shfl_xor_sync(~0u, s, o);
    if ((t & 31) == 0) red[t >> 5] = s;
    __syncthreads();
    if (t < 32) {
        float ss = (t < 8) ? red[t] : 0.f;
#pragma unroll
        for (int o = 4; o > 0; o >>= 1) ss += __shfl_xor_sync(~0u, ss, o);
        if (t == 0) red[0] = rsqrtf(ss / (float)DIM + 1e-6f);
    }
    __syncthreads();
    float rs = red[0];
    float4* o4 = (float4*)(out + (size_t)row * DIM);
    const float4* w4 = (const float4*)w;
#pragma unroll
    for (int i = 0; i < 2; i++) {
        float4 wv = w4[t + i * 256];
        float4 r;
        r.x = v[i].x * rs * wv.x;
        r.y = v[i].y * rs * wv.y;
        r.z = v[i].z * rs * wv.z;
        r.w = v[i].w * rs * wv.w;
        o4[t + i * 256] = r;
    }
}

// ---------------------------------------------------------------------------
// TF32 tensor-core NT GEMM (verified R2): C[m][n] = sum_k A[m][k]*B[n][k]
// ---------------------------------------------------------------------------
#define TBM 128
#define TBN 128
#define TBK 32
#define GEMM_SMEM (2 * (TBM*TBK + TBN*TBK) * 4)  /* 64KB */

__global__ __launch_bounds__(256) void gemm_nt_tf32(const float* __restrict__ A,
                                                    const float* __restrict__ B,
                                                    float* __restrict__ C,
                                                    int M, int N, int K) {
    extern __shared__ uint32_t sm[];
    uint32_t* As = sm;
    uint32_t* Bs = sm + 2 * TBM * TBK;

    int t = threadIdx.x;
    int lane = t & 31, w = t >> 5;
    int wr = w & 3, wc = w >> 2;
    int m0 = blockIdx.y * TBM, n0 = blockIdx.x * TBN;

    float acc[2][8][4];
#pragma unroll
    for (int i = 0; i < 2; i++)
#pragma unroll
        for (int j = 0; j < 8; j++)
#pragma unroll
            for (int e = 0; e < 4; e++) acc[i][j][e] = 0.f;

    float4 Ar[4], Br[4];

#define LOAD_TILES(k0)                                                          \
    _Pragma("unroll")                                                           \
    for (int i = 0; i < 4; i++) {                                               \
        int id = t + i * 256;                                                   \
        int r = id >> 3, q = id & 7;                                            \
        Ar[i] = *(const float4*)(A + (size_t)(m0 + r) * K + (k0) + 4 * q);      \
        Br[i] = *(const float4*)(B + (size_t)(n0 + r) * K + (k0) + 4 * q);      \
    }

#define STORE_TILES(buf)                                                        \
    _Pragma("unroll")                                                           \
    for (int i = 0; i < 4; i++) {                                               \
        int id = t + i * 256;                                                   \
        int r = id >> 3, q = id & 7;                                            \
        int r16 = r & 15;                                                       \
        int fa = (r >> 4) * 4 + (q >> 1);                                       \
        int ja = (r16 >> 3) + 2 * (q & 1);                                      \
        uint32_t* ab = &As[(buf) * (TBM * TBK) + fa * 128 + (r16 & 7) * 16 + ja]; \
        ab[0]  = f2tf(Ar[i].x);                                                 \
        ab[4]  = f2tf(Ar[i].y);                                                 \
        ab[8]  = f2tf(Ar[i].z);                                                 \
        ab[12] = f2tf(Ar[i].w);                                                 \
        int n8 = r & 7;                                                         \
        int fb = (r >> 3) * 4 + (q >> 1);                                       \
        uint32_t* bb = &Bs[(buf) * (TBN * TBK) + fb * 64 + n8 * 8 + (q & 1)];   \
        bb[0] = f2tf(Br[i].x);                                                  \
        bb[2] = f2tf(Br[i].y);                                                  \
        bb[4] = f2tf(Br[i].z);                                                  \
        bb[6] = f2tf(Br[i].w);                                                  \
    }

    LOAD_TILES(0);
    STORE_TILES(0);
    __syncthreads();

    int buf = 0;
    for (int k0 = 0; k0 < K; k0 += TBK) {
        bool has_next = (k0 + TBK) < K;
        if (has_next) { LOAD_TILES(k0 + TBK); }

#pragma unroll
        for (int kt = 0; kt < 4; kt++) {
            uint32_t af[2][4], bf[8][2];
#pragma unroll
            for (int i = 0; i < 2; i++) {
                int mt = wr * 2 + i;
                const uint4 v = *(const uint4*)&As[buf * (TBM * TBK) + (mt * 4 + kt) * 128 + lane * 4];
                af[i][0] = v.x; af[i][1] = v.y; af[i][2] = v.z; af[i][3] = v.w;
            }
#pragma unroll
            for (int j = 0; j < 8; j++) {
                int nt = wc * 8 + j;
                const uint2 v = *(const uint2*)&Bs[buf * (TBN * TBK) + (nt * 4 + kt) * 64 + lane * 2];
                bf[j][0] = v.x; bf[j][1] = v.y;
            }
#pragma unroll
            for (int i = 0; i < 2; i++)
#pragma unroll
                for (int j = 0; j < 8; j++)
                    mma_tf32(acc[i][j], af[i], bf[j]);
        }

        if (has_next) { STORE_TILES(buf ^ 1); }
        __syncthreads();
        buf ^= 1;
    }

#pragma unroll
    for (int i = 0; i < 2; i++) {
#pragma unroll
        for (int j = 0; j < 8; j++) {
            int row = m0 + (wr * 2 + i) * 16 + (lane >> 2);
            int col = n0 + (wc * 8 + j) * 8 + 2 * (lane & 3);
            *(float2*)&C[(size_t)row * N + col] = make_float2(acc[i][j][0], acc[i][j][1]);
            *(float2*)&C[(size_t)(row + 8) * N + col] = make_float2(acc[i][j][2], acc[i][j][3]);
        }
    }
}

// ---------------------------------------------------------------------------
// RoPE in-place on q and k portions of qkv.
// ---------------------------------------------------------------------------
__global__ __launch_bounds__(256) void rope_kernel(float* __restrict__ qkv,
                                                   const float* __restrict__ freqs) {
    int tok = blockIdx.x;
    int s = tok % SEQ;
    for (int idx = threadIdx.x; idx < (NH + NKV) * (HD / 2); idx += blockDim.x) {
        int head = idx >> 6;
        int p = idx & 63;
        float* ptr;
        if (head < NH)
            ptr = qkv + (size_t)tok * QKV_DIM + head * HD;
        else
            ptr = qkv + (size_t)tok * QKV_DIM + NH * HD + (head - NH) * HD;
        float c  = freqs[(s * 64 + p) * 2 + 0];
        float sn = freqs[(s * 64 + p) * 2 + 1];
        float xr = ptr[2 * p];
        float xi = ptr[2 * p + 1];
        ptr[2 * p]     = xr * c - xi * sn;
        ptr[2 * p + 1] = xr * sn + xi * c;
    }
}

// ---------------------------------------------------------------------------
// Tensor-core flash attention v3 (causal, GQA), tf32 mma.sync.
// - Q fragments live in registers (read once via verified smem staging).
// - KV double-buffered: Q's staging region is reused as the 2nd buffer.
// - K gmem loads issued before S-MMAs, V before PV-MMAs (latency hidden).
// - ONE __syncthreads per KV tile.
// - launch_bounds(256,1): no register spills (smem forces 1 CTA/SM anyway).
// ---------------------------------------------------------------------------
#define FQT 128
#define FKT 64
#define PSTR 72
// u32 layout: KVbuf0 @0 (Ks0 8192 | Vs0 @8192, 8192), KVbuf1 @16384, Ps @32768
#define PS_OFF 32768
#define FLASH_SMEM ((32768 + 128*PSTR) * 4)   /* 167936 B */

__global__ __launch_bounds__(256, 1) void flash_tc(const float* __restrict__ qkv,
                                                   float* __restrict__ attn) {
    extern __shared__ uint32_t sm[];
    uint32_t* Ps = sm + PS_OFF;

    int bqt = gridDim.x - 1 - blockIdx.x;   // heavy tiles first
    int h = blockIdx.y, b = blockIdx.z;
    int kvh = h >> 2;                       // NH/NKV = 4
    int t = threadIdx.x, lane = t & 31, w = t >> 5;
    int q0 = bqt * FQT;

    const float* qbase = qkv + (size_t)b * SEQ * QKV_DIM + h * HD;
    const float* kbase = qkv + (size_t)b * SEQ * QKV_DIM + NH * HD + kvh * HD;
    const float* vbase = kbase + NKV * HD;

    // ---- Stage Q tile (128x128) into A-frag order in sm[0..16383], tf32 ----
#pragma unroll
    for (int i = 0; i < 16; i++) {
        int id = t + i * 256;
        int r = id >> 5, q = id & 31;
        float4 v = *(const float4*)(qbase + (size_t)(q0 + r) * QKV_DIM + 4 * q);
        int r16 = r & 15;
        uint32_t* p = &sm[((r >> 4) * 16 + (q >> 1)) * 128 + (r16 & 7) * 16 + (r16 >> 3) + 2 * (q & 1)];
        p[0]  = f2tf(v.x);
        p[4]  = f2tf(v.y);
        p[8]  = f2tf(v.z);
        p[12] = f2tf(v.w);
    }
    __syncthreads();

    // ---- Q fragments -> registers (64 regs), then free the staging region ----
    uint32_t qa[16][4];
#pragma unroll
    for (int kc = 0; kc < 16; kc++)
        *(uint4*)qa[kc] = *(const uint4*)&sm[(w * 16 + kc) * 128 + lane * 4];
    __syncthreads();

    // ---- Stage KV tile 0 into buffer 0 ----
#pragma unroll
    for (int i = 0; i < 8; i++) {
        int id = t + i * 256;
        int r = id >> 5, q = id & 31;
        float4 kk = *(const float4*)(kbase + (size_t)r * QKV_DIM + 4 * q);
        float4 vv = *(const float4*)(vbase + (size_t)r * QKV_DIM + 4 * q);
        uint32_t* kp = &sm[((r >> 3) * 16 + (q >> 1)) * 64 + (r & 7) * 8 + (q & 1)];
        kp[0] = f2tf(kk.x); kp[2] = f2tf(kk.y); kp[4] = f2tf(kk.z); kp[6] = f2tf(kk.w);
        uint32_t* vp = &sm[8192 + ((q >> 1) * 8 + (r >> 3)) * 64 + (16 * (q & 1) + (r & 3)) * 2 + ((r >> 2) & 1)];
        vp[0] = f2tf(vv.x); vp[8] = f2tf(vv.y); vp[16] = f2tf(vv.z); vp[24] = f2tf(vv.w);
    }

    float m0 = -1e30f, m1 = -1e30f, l0 = 0.f, l1 = 0.f;
    float O[16][4];
#pragma unroll
    for (int nt = 0; nt < 16; nt++)
#pragma unroll
        for (int e = 0; e < 4; e++) O[nt][e] = 0.f;

    const float scale = 0.08838834764831845f;  // 1/sqrt(128)
    int g = lane >> 2;
    int row0 = q0 + w * 16 + g;
    int ntiles = 2 * bqt + 2;

    for (int kt = 0; kt < ntiles; kt++) {
        int buf = kt & 1;
        const uint32_t* Ks = sm + buf * 16384;
        const uint32_t* Vs = Ks + 8192;
        bool has_next = (kt + 1) < ntiles;
        int k0 = kt * FKT;
        int k0n = k0 + FKT;

        // prefetch next K tile into registers (latency hidden under S-MMAs)
        float4 Kr[8];
        if (has_next) {
#pragma unroll
            for (int i = 0; i < 8; i++) {
                int id = t + i * 256;
                int r = id >> 5, q = id & 31;
                Kr[i] = *(const float4*)(kbase + (size_t)(k0n + r) * QKV_DIM + 4 * q);
            }
        }

        __syncthreads();   // staging stores of this buf (prev iter / prologue) visible

        // ---- S = Q K^T : 16 rows x 64 cols per warp ----
        float sacc[8][4];
#pragma unroll
        for (int j = 0; j < 8; j++)
#pragma unroll
            for (int e = 0; e < 4; e++) sacc[j][e] = 0.f;

#pragma unroll
        for (int kc = 0; kc < 16; kc++) {
#pragma unroll
            for (int j = 0; j < 8; j++) {
                uint32_t bf[2];
                *(uint2*)bf = *(const uint2*)&Ks[(j * 16 + kc) * 64 + lane * 2];
                mma_tf32(sacc[j], qa[kc], bf);
            }
        }

#pragma unroll
        for (int j = 0; j < 8; j++)
#pragma unroll
            for (int e = 0; e < 4; e++) sacc[j][e] *= scale;

        if (k0 + FKT - 1 > row0) {
            int colb = k0 + 2 * (lane & 3);
#pragma unroll
            for (int j = 0; j < 8; j++) {
                int c = colb + j * 8;
                if (c > row0)     sacc[j][0] = -1e30f;
                if (c + 1 > row0) sacc[j][1] = -1e30f;
                if (c > row0 + 8)     sacc[j][2] = -1e30f;
                if (c + 1 > row0 + 8) sacc[j][3] = -1e30f;
            }
        }

        // ---- register softmax (row = quad; shfl over lane&3) ----
        float mx0 = -1e30f, mx1 = -1e30f;
#pragma unroll
        for (int j = 0; j < 8; j++) {
            mx0 = fmaxf(mx0, fmaxf(sacc[j][0], sacc[j][1]));
            mx1 = fmaxf(mx1, fmaxf(sacc[j][2], sacc[j][3]));
        }
        mx0 = fmaxf(mx0, __shfl_xor_sync(~0u, mx0, 1));
        mx0 = fmaxf(mx0, __shfl_xor_sync(~0u, mx0, 2));
        mx1 = fmaxf(mx1, __shfl_xor_sync(~0u, mx1, 1));
        mx1 = fmaxf(mx1, __shfl_xor_sync(~0u, mx1, 2));
        float mn0 = fmaxf(m0, mx0), mn1 = fmaxf(m1, mx1);
        float al0 = __expf(m0 - mn0), al1 = __expf(m1 - mn1);
        m0 = mn0; m1 = mn1;

        // prefetch next V tile (latency hidden under P-store + PV-MMAs)
        float4 Vr[8];
        if (has_next) {
#pragma unroll
            for (int i = 0; i < 8; i++) {
                int id = t + i * 256;
                int r = id >> 5, q = id & 31;
                Vr[i] = *(const float4*)(vbase + (size_t)(k0n + r) * QKV_DIM + 4 * q);
            }
        }

        float s0 = 0.f, s1 = 0.f;
        uint32_t* prow = &Ps[(w * 16 + g) * PSTR + 2 * (lane & 3)];
#pragma unroll
        for (int j = 0; j < 8; j++) {
            float p0 = __expf(sacc[j][0] - mn0);
            float p1 = __expf(sacc[j][1] - mn0);
            float p2 = __expf(sacc[j][2] - mn1);
            float p3 = __expf(sacc[j][3] - mn1);
            s0 += p0 + p1;
            s1 += p2 + p3;
            uint2 lohi;
            lohi.x = f2tf(p0); lohi.y = f2tf(p1);
            *(uint2*)&prow[j * 8] = lohi;
            lohi.x = f2tf(p2); lohi.y = f2tf(p3);
            *(uint2*)&prow[8 * PSTR + j * 8] = lohi;
        }
        s0 += __shfl_xor_sync(~0u, s0, 1);
        s0 += __shfl_xor_sync(~0u, s0, 2);
        s1 += __shfl_xor_sync(~0u, s1, 1);
        s1 += __shfl_xor_sync(~0u, s1, 2);
        l0 = l0 * al0 + s0;
        l1 = l1 * al1 + s1;

#pragma unroll
        for (int nt = 0; nt < 16; nt++) {
            O[nt][0] *= al0; O[nt][1] *= al0;
            O[nt][2] *= al1; O[nt][3] *= al1;
        }
        __syncwarp();   // P rows warp-private: make cross-lane stores visible

        // ---- O += P V ----
#pragma unroll
        for (int kc = 0; kc < 8; kc++) {
            uint32_t a[4];
            const uint32_t* pb = &Ps[(w * 16 + g) * PSTR + kc * 8 + (lane & 3)];
            a[0] = pb[0];
            a[2] = pb[4];
            a[1] = pb[8 * PSTR];
            a[3] = pb[8 * PSTR + 4];
#pragma unroll
            for (int nt = 0; nt < 16; nt++) {
                uint32_t bf[2];
                *(uint2*)bf = *(const uint2*)&Vs[(nt * 8 + kc) * 64 + lane * 2];
                mma_tf32(O[nt], a, bf);
            }
        }
        __syncwarp();   // PV reads of P done before next tile's P stores

        // ---- store prefetched KV into the other buffer (readers already past) ----
        if (has_next) {
            uint32_t* Kd = sm + (buf ^ 1) * 16384;
            uint32_t* Vd = Kd + 8192;
#pragma unroll
            for (int i = 0; i < 8; i++) {
                int id = t + i * 256;
                int r = id >> 5, q = id & 31;
                uint32_t* kp = &Kd[((r >> 3) * 16 + (q >> 1)) * 64 + (r & 7) * 8 + (q & 1)];
                kp[0] = f2tf(Kr[i].x); kp[2] = f2tf(Kr[i].y);
                kp[4] = f2tf(Kr[i].z); kp[6] = f2tf(Kr[i].w);
                uint32_t* vp = &Vd[((q >> 1) * 8 + (r >> 3)) * 64 + (16 * (q & 1) + (r & 3)) * 2 + ((r >> 2) & 1)];
                vp[0] = f2tf(Vr[i].x); vp[8] = f2tf(Vr[i].y);
                vp[16] = f2tf(Vr[i].z); vp[24] = f2tf(Vr[i].w);
            }
        }
    }

    // ---- epilogue ----
    float inv0 = 1.f / l0, inv1 = 1.f / l1;
    float* ob  = attn + ((size_t)(b * SEQ) + row0) * DIM + h * HD;
    float* ob8 = ob + 8 * DIM;
#pragma unroll
    for (int nt = 0; nt < 16; nt++) {
        int c = nt * 8 + 2 * (lane & 3);
        *(float2*)(ob + c)  = make_float2(O[nt][0] * inv0, O[nt][1] * inv0);
        *(float2*)(ob8 + c) = make_float2(O[nt][2] * inv1, O[nt][3] * inv1);
    }
}

// ---------------------------------------------------------------------------
extern "C" void kernel_launch(void* const* d_in, const int* in_sizes, int n_in,
                              void* d_out, int out_size) {
    (void)in_sizes; (void)n_in; (void)out_size;
    const float* x      = (const float*)d_in[0];
    const float* freqs  = (const float*)d_in[1];
    const float* norm_w = (const float*)d_in[2];
    const float* wqkv   = (const float*)d_in[3];
    const float* wo     = (const float*)d_in[4];
    float* out = (float*)d_out;

    float *xn, *qkv, *attn;
    cudaGetSymbolAddress((void**)&xn, g_xn);
    cudaGetSymbolAddress((void**)&qkv, g_qkv);
    cudaGetSymbolAddress((void**)&attn, g_attn);

    rmsnorm_kernel<<<TOK, 256>>>(x, norm_w, xn);

    cudaFuncSetAttribute(gemm_nt_tf32, cudaFuncAttributeMaxDynamicSharedMemorySize, GEMM_SMEM);
    gemm_nt_tf32<<<dim3(QKV_DIM / TBN, TOK / TBM), 256, GEMM_SMEM>>>(xn, wqkv, qkv, TOK, QKV_DIM, DIM);

    rope_kernel<<<TOK, 256>>>(qkv, freqs);

    cudaFuncSetAttribute(flash_tc, cudaFuncAttributeMaxDynamicSharedMemorySize, FLASH_SMEM);
    flash_tc<<<dim3(SEQ / FQT, NH, BATCH), 256, FLASH_SMEM>>>(qkv, attn);

    gemm_nt_tf32<<<dim3(DIM / TBN, TOK / TBM), 256, GEMM_SMEM>>>(attn, wo, out, TOK, DIM, DIM);
}